// round 5
// baseline (speedup 1.0000x reference)
#include <cuda_runtime.h>
#include <cuda_bf16.h>
#include <math.h>
#include <stdint.h>

// Problem constants
#define BB 512
#define KK 256
#define NN 512
#define CC 6
#define CHUNK 128            // tracks per track-block
#define TPB 128              // threads per block
#define NLAM 64              // lam blocks (8 batches each)
#define MAXTB 2048           // max track blocks = 512 * ceil(512/128)
#define GRID (NLAM + MAXTB)  // 2112

#define LOG2E_F 1.4426950408889634f
#define LN2_F   0.6931471805599453f
#define LOG2PI_LOG2E 2.6514961294723187  // log2(2*pi)

// ---------------- scratch (static device globals; no allocation) -------------
__device__ double4 g_part[GRID];     // {spatial, efs, cnt, 0} per block
__device__ double  g_lam[BB];
__device__ int     g_count[BB];
__device__ int     g_map[MAXTB];     // packed (b<<2)|chunk
__device__ int     g_total;
__device__ unsigned int g_done = 0;

// ---------------- fast math helpers ------------------------------------------
__device__ __forceinline__ float ex2f(float x) {
    float y; asm("ex2.approx.ftz.f32 %0, %1;" : "=f"(y) : "f"(x)); return y;
}
__device__ __forceinline__ float lg2f(float x) {
    float y; asm("lg2.approx.ftz.f32 %0, %1;" : "=f"(y) : "f"(x)); return y;
}
__device__ __forceinline__ double warpRedD(double v) {
    #pragma unroll
    for (int o = 16; o; o >>= 1) v += __shfl_down_sync(0xffffffffu, v, o);
    return v;
}

// ---------------- kernel A: scheduler -----------------------------------------
__global__ __launch_bounds__(512) void sched_kernel(const uint32_t* __restrict__ mask) {
    const int b = threadIdx.x;
    const uint32_t* mb = mask + (size_t)b * NN;

    // prefix-mask count via 3 rounds of parallel probes
    int s1 = 0;
    #pragma unroll
    for (int m = 1; m <= 8; m++) s1 += (mb[64 * m - 1] != 0u);
    int cnt;
    if (s1 == 8) {
        cnt = 512;
    } else {
        const int base1 = 64 * s1;
        int s2 = 0;
        #pragma unroll
        for (int m = 1; m <= 7; m++) s2 += (mb[base1 + 8 * m - 1] != 0u);
        const int base2 = base1 + 8 * s2;
        int s3 = 0;
        #pragma unroll
        for (int o = 0; o < 7; o++) s3 += (mb[base2 + o] != 0u);
        cnt = base2 + s3;
    }

    const int nb = (cnt + CHUNK - 1) / CHUNK;   // 0..4

    // exclusive scan over 512 values (Hillis-Steele)
    __shared__ int sv[512];
    sv[b] = nb;
    __syncthreads();
    for (int off = 1; off < 512; off <<= 1) {
        int v = sv[b];
        int add = (b >= off) ? sv[b - off] : 0;
        __syncthreads();
        sv[b] = v + add;
        __syncthreads();
    }
    const int incl = sv[b];
    const int excl = incl - nb;

    g_count[b] = cnt;
    for (int l = 0; l < nb; l++) g_map[excl + l] = (b << 2) | l;
    if (b == 511) g_total = incl;
}

// ---------------- kernel B: main (lam blocks + track blocks + finalize) -------
__global__ __launch_bounds__(TPB) void main_kernel(
    const float* __restrict__ pi,
    const float* __restrict__ mu,
    const float* __restrict__ L,
    const float* __restrict__ ef_logits,
    const float* __restrict__ tracks,
    float* __restrict__ out)
{
    const int j   = blockIdx.x;
    const int tid = threadIdx.x;
    const int wid = tid >> 5, lid = tid & 31;

    __shared__ float4 scf4[KK];        // {c0,c1,c2,c3}  4 KB
    __shared__ float2 scf2[KK];        // {c4,c5}        2 KB
    __shared__ float  sce[KK * CC];    // ce[k*6+g]      6 KB
    __shared__ double red[4 * 3];
    __shared__ bool   isLast;

    if (j < NLAM) {
        // ---- lam blocks: warp w handles batches j*8 + 2w, +2w+1 ----
        #pragma unroll
        for (int u = 0; u < 2; u++) {
            const int b = j * 8 + wid * 2 + u;
            const float* pb = pi + (size_t)b * KK;
            double lam = 0.0;
            #pragma unroll
            for (int o = 0; o < KK; o += 32) lam += (double)pb[o + lid];
            lam = warpRedD(lam);
            if (lid == 0) g_lam[b] = lam;
        }
        if (tid == 0) g_part[j] = make_double4(0.0, 0.0, 0.0, 0.0);
    } else {
        const int j2 = j - NLAM;
        double spatial = 0.0, efs = 0.0, cntp = 0.0;

        if (j2 < g_total) {
            const int mp   = g_map[j2];
            const int b    = mp >> 2;
            const int n0   = (mp & 3) * CHUNK;
            const int cntb = g_count[b];

            // ---- staging: thread tid builds coefficients for k = tid, tid+128 ----
            #pragma unroll
            for (int kk = 0; kk < 2; kk++) {
                const int k = tid + kk * TPB;
                const int i = b * KK + k;
                double pv = (double)pi[i];
                double a  = (double)L[i * 4 + 0];
                double bb = (double)L[i * 4 + 2];
                double c  = (double)L[i * 4 + 3];
                double m0 = (double)mu[i * 2 + 0];
                double m1 = (double)mu[i * 2 + 1];

                double base2 = log2(pv) - LOG2PI_LOG2E - log2(a * c);  // < 0

                const double RQ2 = 0.72134752044448170;  // 0.5 * log2(e)
                double A2  = RQ2 / (a * a);
                double Cr2 = RQ2 / (c * c);
                double BA  = bb / a;
                double P = A2 + Cr2 * BA * BA;
                double Q = Cr2;
                double R = -2.0 * Cr2 * BA;

                float4 v4;
                float2 v2;
                v4.x = (float)(base2 - P * m0 * m0 - Q * m1 * m1 - R * m0 * m1);
                v4.y = (float)(2.0 * P * m0 + R * m1);
                v4.z = (float)(2.0 * Q * m1 + R * m0);
                v4.w = (float)(-P);
                v2.x = (float)(-Q);
                v2.y = (float)(-R);
                scf4[k] = v4;
                scf2[k] = v2;

                // CE table: lse(ef_logits) - ef_logits[c]
                float e[CC];
                float mx = -INFINITY;
                #pragma unroll
                for (int c2 = 0; c2 < CC; c2++) {
                    e[c2] = ef_logits[(size_t)i * CC + c2];
                    mx = fmaxf(mx, e[c2]);
                }
                float ssum = 0.f;
                #pragma unroll
                for (int c2 = 0; c2 < CC; c2++) ssum += ex2f((e[c2] - mx) * LOG2E_F);
                float lse = mx + lg2f(ssum) * LN2_F;
                #pragma unroll
                for (int c2 = 0; c2 < CC; c2++) sce[k * CC + c2] = lse - e[c2];
            }
            __syncthreads();

            // ---- per-track pass: thread tid owns track n0 + tid ----
            const int n = n0 + tid;
            const bool act = (n < cntb);
            if (__ballot_sync(0xffffffffu, act) != 0u) {
                // tracks memory is valid (finite) even past count
                const float* tr = tracks + ((size_t)b * NN + n) * 6;
                const float x0 = tr[0], x1 = tr[1];
                const int   g  = (int)tr[5];
                const float xx0 = x0 * x0, xx1 = x1 * x1, x01 = x0 * x1;

                float s = 0.f, t = 0.f;
                #pragma unroll 8
                for (int k = 0; k < KK; k++) {
                    float4 c4 = scf4[k];
                    float2 c2 = scf2[k];
                    float q = fmaf(c4.y, x0, c4.x);
                    q = fmaf(c4.z, x1, q);
                    q = fmaf(c4.w, xx0, q);
                    q = fmaf(c2.x, xx1, q);
                    q = fmaf(c2.y, x01, q);
                    float p = ex2f(q);
                    s += p;
                    t = fmaf(p, sce[k * CC + g], t);
                }
                if (act) {
                    spatial = -(double)(lg2f(s) * LN2_F);
                    efs     = (double)(t / s);
                    cntp    = 1.0;
                }
            }
        }

        // ---- block reduce 3 doubles (uniform control, 4 warps) ----
        spatial = warpRedD(spatial);
        efs     = warpRedD(efs);
        cntp    = warpRedD(cntp);
        if (lid == 0) {
            red[wid]     = spatial;
            red[4 + wid] = efs;
            red[8 + wid] = cntp;
        }
        __syncthreads();
        if (tid == 0) {
            double s0 = 0, s1 = 0, s2 = 0;
            #pragma unroll
            for (int w = 0; w < 4; w++) {
                s0 += red[w]; s1 += red[4 + w]; s2 += red[8 + w];
            }
            g_part[j] = make_double4(s0, s1, s2, 0.0);
        }
    }

    // ---- last-block-done finalize (deterministic fixed-order sums) ----
    __threadfence();
    if (tid == 0) {
        unsigned int v = atomicAdd(&g_done, 1u);
        isLast = (v == (unsigned)GRID - 1u);
    }
    __syncthreads();
    if (isLast) {
        double spSum = 0, efSum = 0, cntSum = 0;
        for (int q = tid; q < GRID; q += TPB) {
            double4 e = g_part[q];
            spSum  += e.x;
            efSum  += e.y;
            cntSum += e.z;
        }
        double lamSum = 0, l1Sum = 0;
        for (int b2 = tid; b2 < BB; b2 += TPB) {
            double lm = g_lam[b2];
            double gc = (double)g_count[b2];
            lamSum += lm;
            l1Sum  += fabs(lm - gc) * sqrt(gc + 1.0);
        }
        spSum  = warpRedD(spSum);
        efSum  = warpRedD(efSum);
        cntSum = warpRedD(cntSum);
        lamSum = warpRedD(lamSum);
        l1Sum  = warpRedD(l1Sum);
        __syncthreads();
        __shared__ double red5[4 * 5];
        if (lid == 0) {
            red5[wid]      = spSum;
            red5[4 + wid]  = efSum;
            red5[8 + wid]  = cntSum;
            red5[12 + wid] = lamSum;
            red5[16 + wid] = l1Sum;
        }
        __syncthreads();
        if (tid == 0) {
            double a0 = 0, a1 = 0, a2 = 0, a3 = 0, a4 = 0;
            #pragma unroll
            for (int w = 0; w < 4; w++) {
                a0 += red5[w]; a1 += red5[4 + w]; a2 += red5[8 + w];
                a3 += red5[12 + w]; a4 += red5[16 + w];
            }
            double n_total    = a2 > 1.0 ? a2 : 1.0;
            double spatialL   = a0 / n_total;
            double efL        = a1 / n_total;
            double count_loss = a3 / (double)BB;
            double count_l1   = a4 / (double)BB;
            double total = count_loss + spatialL + efL + count_l1;
            out[0] = (float)total;
            out[1] = (float)spatialL;
            out[2] = (float)count_loss;
            out[3] = (float)count_l1;
            out[4] = (float)efL;
            g_done = 0;  // reset for next graph replay
        }
    }
}

// ---------------- launch -------------------------------------------------------
extern "C" void kernel_launch(void* const* d_in, const int* in_sizes, int n_in,
                              void* d_out, int out_size) {
    const float* pi        = (const float*)d_in[0];
    const float* mu        = (const float*)d_in[1];
    const float* L         = (const float*)d_in[2];
    const float* ef_logits = (const float*)d_in[3];
    const float* tracks    = (const float*)d_in[4];
    const uint32_t* mask   = (const uint32_t*)d_in[5];

    sched_kernel<<<1, 512>>>(mask);
    main_kernel<<<GRID, TPB>>>(pi, mu, L, ef_logits, tracks, (float*)d_out);
}